// round 4
// baseline (speedup 1.0000x reference)
#include <cuda_runtime.h>
#include <cstdint>

#define NODES_MAX 100000
#define FDIM 64
#define RPB 128            // rows per block (gemm v2)
#define RPT 4              // rows per thread
#define CPG 8              // cols per thread
#define PITCH 132          // padded row pitch for transposed smem (4-float aligned, conflict-free)

// Scratch (allocation-free rule: __device__ globals)
__device__ float g_dinv[NODES_MAX];
__device__ float g_xws[NODES_MAX * FDIM];
__device__ float g_agg[NODES_MAX * FDIM];

// ---------------------------------------------------------------------------
// Degrees
// ---------------------------------------------------------------------------
__global__ void k_deg_init(float* deg, int n) {
    int i = blockIdx.x * blockDim.x + threadIdx.x;
    if (i < n) deg[i] = 1.0f;
}
__global__ void k_deg_count(const int* __restrict__ dst, float* deg, int E) {
    int e = blockIdx.x * blockDim.x + threadIdx.x;
    if (e < E) atomicAdd(&deg[dst[e]], 1.0f);
}
__global__ void k_deg_rsqrt(float* deg, int n) {
    int i = blockIdx.x * blockDim.x + threadIdx.x;
    if (i < n) deg[i] = rsqrtf(deg[i]);
}

// ---------------------------------------------------------------------------
// GEMM + GCN epilogue, 4x8 register tile per thread.
//   acc = f(in[rows]) @ W ; xws = acc*dinv ; agg = acc*dinv^2
// Block: 128 rows x 64 cols, 256 threads (32 lanes x 8 warps).
// Thread (lane, cg): rows lane*4..+3, cols cg*8..+7.
// Input staged TRANSPOSED: rbT[k][row] (pitch 132) -> one LDS.128 per k
// fetches the thread's 4 row-values; W reads are warp-broadcast LDS.128.
// ---------------------------------------------------------------------------
template<bool PRE>
__global__ void __launch_bounds__(256, 4) k_gemm64(
        const float* __restrict__ in, const float* __restrict__ W,
        const float* __restrict__ bin, const float* __restrict__ dinv,
        float* __restrict__ xws, float* __restrict__ agg, int n) {
    __shared__ float Ws[FDIM * FDIM];
    __shared__ float rbT[FDIM * PITCH];
    const int lane = threadIdx.x;
    const int cg   = threadIdx.y;
    const int tid  = cg * 32 + lane;
    const int row0 = blockIdx.x * RPB;

    // stage W
    {
        const float4* W4 = (const float4*)W;
        float4* Ws4 = (float4*)Ws;
        #pragma unroll
        for (int i = tid; i < FDIM * FDIM / 4; i += 256) Ws4[i] = W4[i];
    }
    // stage input transposed (coalesced gmem read; 4-way smem store conflict ok)
    #pragma unroll
    for (int i = tid; i < RPB * FDIM; i += 256) {
        int r = i >> 6, c = i & 63;
        int row = row0 + r;
        float v = (row < n) ? in[row * FDIM + c] : 0.0f;
        if (PRE) v = fmaxf(v + bin[c], 0.0f);
        rbT[c * PITCH + r] = v;
    }
    __syncthreads();

    float acc[RPT][CPG];
    #pragma unroll
    for (int i = 0; i < RPT; i++)
        #pragma unroll
        for (int j = 0; j < CPG; j++) acc[i][j] = 0.0f;

    #pragma unroll
    for (int k = 0; k < FDIM; k++) {
        float4 a  = *(const float4*)&rbT[k * PITCH + lane * RPT];
        float4 w0 = *(const float4*)&Ws[k * FDIM + cg * CPG];
        float4 w1 = *(const float4*)&Ws[k * FDIM + cg * CPG + 4];
        const float ar[RPT] = {a.x, a.y, a.z, a.w};
        #pragma unroll
        for (int i = 0; i < RPT; i++) {
            acc[i][0] = fmaf(ar[i], w0.x, acc[i][0]);
            acc[i][1] = fmaf(ar[i], w0.y, acc[i][1]);
            acc[i][2] = fmaf(ar[i], w0.z, acc[i][2]);
            acc[i][3] = fmaf(ar[i], w0.w, acc[i][3]);
            acc[i][4] = fmaf(ar[i], w1.x, acc[i][4]);
            acc[i][5] = fmaf(ar[i], w1.y, acc[i][5]);
            acc[i][6] = fmaf(ar[i], w1.z, acc[i][6]);
            acc[i][7] = fmaf(ar[i], w1.w, acc[i][7]);
        }
    }

    #pragma unroll
    for (int i = 0; i < RPT; i++) {
        int row = row0 + lane * RPT + i;
        if (row >= n) break;
        float di = dinv[row];
        float di2 = di * di;
        float4 s0, s1, a0, a1;
        s0.x = acc[i][0]*di; s0.y = acc[i][1]*di; s0.z = acc[i][2]*di; s0.w = acc[i][3]*di;
        s1.x = acc[i][4]*di; s1.y = acc[i][5]*di; s1.z = acc[i][6]*di; s1.w = acc[i][7]*di;
        a0.x = acc[i][0]*di2; a0.y = acc[i][1]*di2; a0.z = acc[i][2]*di2; a0.w = acc[i][3]*di2;
        a1.x = acc[i][4]*di2; a1.y = acc[i][5]*di2; a1.z = acc[i][6]*di2; a1.w = acc[i][7]*di2;
        float* xp = xws + row * FDIM + cg * CPG;
        float* ap = agg + row * FDIM + cg * CPG;
        *(float4*)(xp)     = s0;
        *(float4*)(xp + 4) = s1;
        *(float4*)(ap)     = a0;
        *(float4*)(ap + 4) = a1;
    }
}

// ---------------------------------------------------------------------------
// Edge scatter: agg[dst,:] += xws[src,:] * dinv[dst]; 16 lanes/edge, vector RED.
// ---------------------------------------------------------------------------
__global__ void k_scatter(const int* __restrict__ src, const int* __restrict__ dst,
                          const float* __restrict__ dinv,
                          const float4* __restrict__ xws, float4* __restrict__ agg, int E) {
    int t = blockIdx.x * blockDim.x + threadIdx.x;
    int e = t >> 4;
    if (e >= E) return;
    int lane = t & 15;
    int s = src[e];
    int d = dst[e];
    float nd = dinv[d];
    float4 v = __ldg(&xws[s * 16 + lane]);
    v.x *= nd; v.y *= nd; v.z *= nd; v.w *= nd;
    float4* p = &agg[d * 16 + lane];
    asm volatile("red.global.add.v4.f32 [%0], {%1, %2, %3, %4};"
                 :: "l"(p), "f"(v.x), "f"(v.y), "f"(v.z), "f"(v.w) : "memory");
}

// ---------------------------------------------------------------------------
// Head: v = relu(agg + b2); h = relu(v @ dW1 + db1); out = h @ dW2 + db2
// Same 4x8 register-tile structure; transposed buffer reused for v and h.
// ---------------------------------------------------------------------------
__global__ void __launch_bounds__(256, 4) k_head(
        const float* __restrict__ agg, const float* __restrict__ b2,
        const float* __restrict__ dW1, const float* __restrict__ db1,
        const float* __restrict__ dW2, const float* __restrict__ db2,
        float* __restrict__ out, int n) {
    __shared__ float sW1[FDIM * FDIM];
    __shared__ float sW2[FDIM * 16];
    __shared__ float sb[2 * FDIM + 16];       // b2 | db1 | db2
    __shared__ float tT[FDIM * PITCH];        // transposed v, then reused for h
    const int lane = threadIdx.x;
    const int cg   = threadIdx.y;
    const int tid  = cg * 32 + lane;
    const int row0 = blockIdx.x * RPB;

    {
        const float4* a4 = (const float4*)dW1;
        float4* s4 = (float4*)sW1;
        #pragma unroll
        for (int i = tid; i < FDIM * FDIM / 4; i += 256) s4[i] = a4[i];
        const float4* b4 = (const float4*)dW2;
        float4* t4 = (float4*)sW2;
        if (tid < FDIM * 16 / 4) t4[tid] = b4[tid];
        if (tid < 64)        sb[tid] = b2[tid];
        else if (tid < 128)  sb[tid] = db1[tid - 64];
        else if (tid < 144)  sb[tid] = db2[tid - 128];
    }

    // vT = relu(agg + b2), transposed
    #pragma unroll
    for (int i = tid; i < RPB * FDIM; i += 256) {
        int r = i >> 6, c = i & 63;
        int row = row0 + r;
        float x = (row < n) ? agg[row * FDIM + c] : 0.0f;
        tT[c * PITCH + r] = fmaxf(x + b2[c], 0.0f);
    }
    __syncthreads();

    // h = relu(v @ dW1 + db1), 4x8 tile
    float acc[RPT][CPG];
    #pragma unroll
    for (int i = 0; i < RPT; i++)
        #pragma unroll
        for (int j = 0; j < CPG; j++) acc[i][j] = 0.0f;

    #pragma unroll
    for (int k = 0; k < FDIM; k++) {
        float4 a  = *(const float4*)&tT[k * PITCH + lane * RPT];
        float4 w0 = *(const float4*)&sW1[k * FDIM + cg * CPG];
        float4 w1 = *(const float4*)&sW1[k * FDIM + cg * CPG + 4];
        const float ar[RPT] = {a.x, a.y, a.z, a.w};
        #pragma unroll
        for (int i = 0; i < RPT; i++) {
            acc[i][0] = fmaf(ar[i], w0.x, acc[i][0]);
            acc[i][1] = fmaf(ar[i], w0.y, acc[i][1]);
            acc[i][2] = fmaf(ar[i], w0.z, acc[i][2]);
            acc[i][3] = fmaf(ar[i], w0.w, acc[i][3]);
            acc[i][4] = fmaf(ar[i], w1.x, acc[i][4]);
            acc[i][5] = fmaf(ar[i], w1.y, acc[i][5]);
            acc[i][6] = fmaf(ar[i], w1.z, acc[i][6]);
            acc[i][7] = fmaf(ar[i], w1.w, acc[i][7]);
        }
    }
    __syncthreads();   // all reads of vT done before overwrite with h

    #pragma unroll
    for (int i = 0; i < RPT; i++)
        #pragma unroll
        for (int j = 0; j < CPG; j++)
            tT[(cg * CPG + j) * PITCH + lane * RPT + i] =
                fmaxf(acc[i][j] + sb[64 + cg * CPG + j], 0.0f);
    __syncthreads();

    // out = h @ dW2 + db2 : 4 rows x 2 cols per thread
    {
        float o[RPT][2];
        #pragma unroll
        for (int i = 0; i < RPT; i++) { o[i][0] = 0.0f; o[i][1] = 0.0f; }
        #pragma unroll
        for (int k = 0; k < FDIM; k++) {
            float4 a = *(const float4*)&tT[k * PITCH + lane * RPT];
            float2 w = *(const float2*)&sW2[k * 16 + cg * 2];
            const float ar[RPT] = {a.x, a.y, a.z, a.w};
            #pragma unroll
            for (int i = 0; i < RPT; i++) {
                o[i][0] = fmaf(ar[i], w.x, o[i][0]);
                o[i][1] = fmaf(ar[i], w.y, o[i][1]);
            }
        }
        #pragma unroll
        for (int i = 0; i < RPT; i++) {
            int row = row0 + lane * RPT + i;
            if (row >= n) break;
            float2 v;
            v.x = o[i][0] + sb[128 + cg * 2];
            v.y = o[i][1] + sb[128 + cg * 2 + 1];
            *(float2*)&out[row * 16 + cg * 2] = v;
        }
    }
}

// ---------------------------------------------------------------------------
extern "C" void kernel_launch(void* const* d_in, const int* in_sizes, int n_in,
                              void* d_out, int out_size) {
    const float* x   = (const float*)d_in[0];
    const int*   ei  = (const int*)  d_in[1];
    const float* W1  = (const float*)d_in[2];
    const float* b1  = (const float*)d_in[3];
    const float* W2  = (const float*)d_in[4];
    const float* b2  = (const float*)d_in[5];
    const float* dW1 = (const float*)d_in[6];
    const float* db1 = (const float*)d_in[7];
    const float* dW2 = (const float*)d_in[8];
    const float* db2 = (const float*)d_in[9];
    float* out = (float*)d_out;

    const int N = in_sizes[0] / FDIM;
    const int E = in_sizes[1] / 2;
    const int* src = ei;
    const int* dst = ei + E;

    float* dinv; float* xws; float* agg;
    cudaGetSymbolAddress((void**)&dinv, g_dinv);
    cudaGetSymbolAddress((void**)&xws, g_xws);
    cudaGetSymbolAddress((void**)&agg, g_agg);

    const int TB = 256;
    dim3 gblk(32, 8);
    const int rowBlocks = (N + RPB - 1) / RPB;

    k_deg_init <<<(N + TB - 1) / TB, TB>>>(dinv, N);
    k_deg_count<<<(E + TB - 1) / TB, TB>>>(dst, dinv, E);
    k_deg_rsqrt<<<(N + TB - 1) / TB, TB>>>(dinv, N);

    k_gemm64<false><<<rowBlocks, gblk>>>(x, W1, nullptr, dinv, xws, agg, N);
    k_scatter<<<((long long)E * 16 + TB - 1) / TB, TB>>>(src, dst, dinv,
                                                         (const float4*)xws, (float4*)agg, E);
    k_gemm64<true><<<rowBlocks, gblk>>>(agg, W2, b1, dinv, xws, agg, N);
    k_scatter<<<((long long)E * 16 + TB - 1) / TB, TB>>>(src, dst, dinv,
                                                         (const float4*)xws, (float4*)agg, E);

    k_head<<<rowBlocks, gblk>>>(agg, b2, dW1, db1, dW2, db2, out, N);
}

// round 5
// speedup vs baseline: 1.3892x; 1.3892x over previous
#include <cuda_runtime.h>
#include <cstdint>

#define NODES_MAX 100000
#define EDGES_MAX 1600000
#define FDIM 64
#define RPB 64             // rows per block
#define RPT 2              // rows per thread
#define CPG 8              // cols per thread
#define PITCH 66           // transposed smem pitch (floats)
#define SCAN_B 1024

// Scratch (allocation-free rule: __device__ globals)
__device__ float g_dinv[NODES_MAX];
__device__ float g_xws[NODES_MAX * FDIM];     // (x @ W) * dinv[row]
__device__ float g_agg[NODES_MAX * FDIM];     // gathered output
__device__ int   g_cnt[NODES_MAX];            // in-degree (dst count)
__device__ int   g_rowptr[NODES_MAX];
__device__ int   g_wptr[NODES_MAX];
__device__ int   g_eidx[EDGES_MAX];           // CSR: src ids grouped by dst
__device__ int   g_bsum[128];

// ---------------------------------------------------------------------------
// CSR build: count, dinv, 3-phase exclusive scan, fill
// ---------------------------------------------------------------------------
__global__ void k_cnt_zero(int* cnt, int n) {
    int i = blockIdx.x * blockDim.x + threadIdx.x;
    if (i < n) cnt[i] = 0;
}
__global__ void k_count(const int* __restrict__ dst, int* cnt, int E) {
    int e = blockIdx.x * blockDim.x + threadIdx.x;
    if (e < E) atomicAdd(&cnt[dst[e]], 1);
}
__global__ void k_dinv(const int* __restrict__ cnt, float* dinv, int n) {
    int i = blockIdx.x * blockDim.x + threadIdx.x;
    if (i < n) dinv[i] = rsqrtf((float)(cnt[i] + 1));
}
__global__ void k_scan1(const int* __restrict__ cnt, int* rowptr, int* bsum, int n) {
    __shared__ int sm[SCAN_B];
    int i = blockIdx.x * SCAN_B + threadIdx.x;
    int v = (i < n) ? cnt[i] : 0;
    sm[threadIdx.x] = v;
    __syncthreads();
    #pragma unroll
    for (int off = 1; off < SCAN_B; off <<= 1) {
        int t = (threadIdx.x >= off) ? sm[threadIdx.x - off] : 0;
        __syncthreads();
        sm[threadIdx.x] += t;
        __syncthreads();
    }
    if (i < n) rowptr[i] = sm[threadIdx.x] - v;     // exclusive
    if (threadIdx.x == SCAN_B - 1) bsum[blockIdx.x] = sm[SCAN_B - 1];
}
__global__ void k_scan2(int* bsum, int nb) {
    __shared__ int sm[128];
    int v = (threadIdx.x < nb) ? bsum[threadIdx.x] : 0;
    sm[threadIdx.x] = v;
    __syncthreads();
    #pragma unroll
    for (int off = 1; off < 128; off <<= 1) {
        int t = (threadIdx.x >= off) ? sm[threadIdx.x - off] : 0;
        __syncthreads();
        sm[threadIdx.x] += t;
        __syncthreads();
    }
    if (threadIdx.x < nb) bsum[threadIdx.x] = sm[threadIdx.x] - v;   // exclusive
}
__global__ void k_scan3(int* rowptr, int* wptr, const int* __restrict__ bsum, int n) {
    int i = blockIdx.x * blockDim.x + threadIdx.x;
    if (i < n) {
        int r = rowptr[i] + bsum[i >> 10];
        rowptr[i] = r;
        wptr[i] = r;
    }
}
__global__ void k_fill(const int* __restrict__ src, const int* __restrict__ dst,
                       int* wptr, int* eidx, int E) {
    int e = blockIdx.x * blockDim.x + threadIdx.x;
    if (e < E) {
        int d = dst[e];
        int p = atomicAdd(&wptr[d], 1);
        eidx[p] = src[e];
    }
}

// ---------------------------------------------------------------------------
// GEMM: xws[row] = (f(in[row]) @ W) * dinv[row]   (PRE: f(v)=relu(v+bin))
// Block 64 rows x 64 cols, 256 threads (32 lanes x 8 warps), 2x8 tile/thread.
// Input staged transposed: one LDS.64 per k fetches the thread's 2 rows.
// ---------------------------------------------------------------------------
template<bool PRE>
__global__ void __launch_bounds__(256, 6) k_gemm64(
        const float* __restrict__ in, const float* __restrict__ W,
        const float* __restrict__ bin, const float* __restrict__ dinv,
        float* __restrict__ xws, int n) {
    __shared__ float Ws[FDIM * FDIM];
    __shared__ float rbT[FDIM * PITCH];
    const int lane = threadIdx.x;
    const int cg   = threadIdx.y;
    const int tid  = cg * 32 + lane;
    const int row0 = blockIdx.x * RPB;

    {
        const float4* W4 = (const float4*)W;
        float4* Ws4 = (float4*)Ws;
        #pragma unroll
        for (int i = tid; i < FDIM * FDIM / 4; i += 256) Ws4[i] = W4[i];
    }
    #pragma unroll
    for (int i = tid; i < RPB * FDIM; i += 256) {
        int r = i >> 6, c = i & 63;
        int row = row0 + r;
        float v = (row < n) ? in[row * FDIM + c] : 0.0f;
        if (PRE) v = fmaxf(v + bin[c], 0.0f);
        rbT[c * PITCH + r] = v;
    }
    __syncthreads();

    float acc[RPT][CPG];
    #pragma unroll
    for (int i = 0; i < RPT; i++)
        #pragma unroll
        for (int j = 0; j < CPG; j++) acc[i][j] = 0.0f;

    #pragma unroll
    for (int k = 0; k < FDIM; k++) {
        float2 a  = *(const float2*)&rbT[k * PITCH + lane * RPT];
        float4 w0 = *(const float4*)&Ws[k * FDIM + cg * CPG];
        float4 w1 = *(const float4*)&Ws[k * FDIM + cg * CPG + 4];
        const float ar[RPT] = {a.x, a.y};
        #pragma unroll
        for (int i = 0; i < RPT; i++) {
            acc[i][0] = fmaf(ar[i], w0.x, acc[i][0]);
            acc[i][1] = fmaf(ar[i], w0.y, acc[i][1]);
            acc[i][2] = fmaf(ar[i], w0.z, acc[i][2]);
            acc[i][3] = fmaf(ar[i], w0.w, acc[i][3]);
            acc[i][4] = fmaf(ar[i], w1.x, acc[i][4]);
            acc[i][5] = fmaf(ar[i], w1.y, acc[i][5]);
            acc[i][6] = fmaf(ar[i], w1.z, acc[i][6]);
            acc[i][7] = fmaf(ar[i], w1.w, acc[i][7]);
        }
    }

    #pragma unroll
    for (int i = 0; i < RPT; i++) {
        int row = row0 + lane * RPT + i;
        if (row >= n) break;
        float di = dinv[row];
        float4 s0, s1;
        s0.x = acc[i][0]*di; s0.y = acc[i][1]*di; s0.z = acc[i][2]*di; s0.w = acc[i][3]*di;
        s1.x = acc[i][4]*di; s1.y = acc[i][5]*di; s1.z = acc[i][6]*di; s1.w = acc[i][7]*di;
        float* xp = xws + row * FDIM + cg * CPG;
        *(float4*)(xp)     = s0;
        *(float4*)(xp + 4) = s1;
    }
}

// ---------------------------------------------------------------------------
// CSR gather (replaces atomic scatter):
//   agg[d] = dinv[d] * (xws[d] + Σ_{s in N(d)} xws[s])
// One warp per dst node; lane owns one float2 (2 of 64 cols).
// Edge ids staged 32-at-a-time via shfl broadcast.
// ---------------------------------------------------------------------------
__global__ void k_gather(const int* __restrict__ rowptr, const int* __restrict__ cnt,
                         const int* __restrict__ eidx, const float* __restrict__ dinv,
                         const float2* __restrict__ xws, float2* __restrict__ agg, int n) {
    int warp = (blockIdx.x * blockDim.x + threadIdx.x) >> 5;
    if (warp >= n) return;
    int lane = threadIdx.x & 31;
    int start = rowptr[warp];
    int deg   = cnt[warp];

    float2 acc = __ldg(&xws[warp * 32 + lane]);   // self loop
    for (int base = 0; base < deg; base += 32) {
        int m = min(32, deg - base);
        int e = 0;
        if (lane < m) e = eidx[start + base + lane];
        #pragma unroll 4
        for (int j = 0; j < m; j++) {
            int s = __shfl_sync(0xffffffffu, e, j);
            float2 v = __ldg(&xws[s * 32 + lane]);
            acc.x += v.x;
            acc.y += v.y;
        }
    }
    float nd = dinv[warp];
    acc.x *= nd; acc.y *= nd;
    agg[warp * 32 + lane] = acc;
}

// ---------------------------------------------------------------------------
// Head: v = relu(agg + b2); h = relu(v @ dW1 + db1); out = h @ dW2 + db2
// Same 2x8 register-tile structure; transposed buffer reused for v and h.
// ---------------------------------------------------------------------------
__global__ void __launch_bounds__(256, 5) k_head(
        const float* __restrict__ agg, const float* __restrict__ b2,
        const float* __restrict__ dW1, const float* __restrict__ db1,
        const float* __restrict__ dW2, const float* __restrict__ db2,
        float* __restrict__ out, int n) {
    __shared__ float sW1[FDIM * FDIM];
    __shared__ float sW2[FDIM * 16];
    __shared__ float sb[2 * FDIM + 16];       // b2 | db1 | db2
    __shared__ float tT[FDIM * PITCH];        // transposed v, reused for h
    const int lane = threadIdx.x;
    const int cg   = threadIdx.y;
    const int tid  = cg * 32 + lane;
    const int row0 = blockIdx.x * RPB;

    {
        const float4* a4 = (const float4*)dW1;
        float4* s4 = (float4*)sW1;
        #pragma unroll
        for (int i = tid; i < FDIM * FDIM / 4; i += 256) s4[i] = a4[i];
        const float4* b4 = (const float4*)dW2;
        float4* t4 = (float4*)sW2;
        if (tid < FDIM * 16 / 4) t4[tid] = b4[tid];
        if (tid < 64)        sb[tid] = b2[tid];
        else if (tid < 128)  sb[tid] = db1[tid - 64];
        else if (tid < 144)  sb[tid] = db2[tid - 128];
    }

    #pragma unroll
    for (int i = tid; i < RPB * FDIM; i += 256) {
        int r = i >> 6, c = i & 63;
        int row = row0 + r;
        float x = (row < n) ? agg[row * FDIM + c] : 0.0f;
        tT[c * PITCH + r] = fmaxf(x + b2[c], 0.0f);
    }
    __syncthreads();

    float acc[RPT][CPG];
    #pragma unroll
    for (int i = 0; i < RPT; i++)
        #pragma unroll
        for (int j = 0; j < CPG; j++) acc[i][j] = 0.0f;

    #pragma unroll
    for (int k = 0; k < FDIM; k++) {
        float2 a  = *(const float2*)&tT[k * PITCH + lane * RPT];
        float4 w0 = *(const float4*)&sW1[k * FDIM + cg * CPG];
        float4 w1 = *(const float4*)&sW1[k * FDIM + cg * CPG + 4];
        const float ar[RPT] = {a.x, a.y};
        #pragma unroll
        for (int i = 0; i < RPT; i++) {
            acc[i][0] = fmaf(ar[i], w0.x, acc[i][0]);
            acc[i][1] = fmaf(ar[i], w0.y, acc[i][1]);
            acc[i][2] = fmaf(ar[i], w0.z, acc[i][2]);
            acc[i][3] = fmaf(ar[i], w0.w, acc[i][3]);
            acc[i][4] = fmaf(ar[i], w1.x, acc[i][4]);
            acc[i][5] = fmaf(ar[i], w1.y, acc[i][5]);
            acc[i][6] = fmaf(ar[i], w1.z, acc[i][6]);
            acc[i][7] = fmaf(ar[i], w1.w, acc[i][7]);
        }
    }
    __syncthreads();   // vT reads complete before overwrite with h

    #pragma unroll
    for (int i = 0; i < RPT; i++)
        #pragma unroll
        for (int j = 0; j < CPG; j++)
            tT[(cg * CPG + j) * PITCH + lane * RPT + i] =
                fmaxf(acc[i][j] + sb[64 + cg * CPG + j], 0.0f);
    __syncthreads();

    {
        float o[RPT][2];
        #pragma unroll
        for (int i = 0; i < RPT; i++) { o[i][0] = 0.0f; o[i][1] = 0.0f; }
        #pragma unroll
        for (int k = 0; k < FDIM; k++) {
            float2 a = *(const float2*)&tT[k * PITCH + lane * RPT];
            float2 w = *(const float2*)&sW2[k * 16 + cg * 2];
            const float ar[RPT] = {a.x, a.y};
            #pragma unroll
            for (int i = 0; i < RPT; i++) {
                o[i][0] = fmaf(ar[i], w.x, o[i][0]);
                o[i][1] = fmaf(ar[i], w.y, o[i][1]);
            }
        }
        #pragma unroll
        for (int i = 0; i < RPT; i++) {
            int row = row0 + lane * RPT + i;
            if (row >= n) break;
            float2 v;
            v.x = o[i][0] + sb[128 + cg * 2];
            v.y = o[i][1] + sb[128 + cg * 2 + 1];
            *(float2*)&out[row * 16 + cg * 2] = v;
        }
    }
}

// ---------------------------------------------------------------------------
extern "C" void kernel_launch(void* const* d_in, const int* in_sizes, int n_in,
                              void* d_out, int out_size) {
    const float* x   = (const float*)d_in[0];
    const int*   ei  = (const int*)  d_in[1];
    const float* W1  = (const float*)d_in[2];
    const float* b1  = (const float*)d_in[3];
    const float* W2  = (const float*)d_in[4];
    const float* b2  = (const float*)d_in[5];
    const float* dW1 = (const float*)d_in[6];
    const float* db1 = (const float*)d_in[7];
    const float* dW2 = (const float*)d_in[8];
    const float* db2 = (const float*)d_in[9];
    float* out = (float*)d_out;

    const int N = in_sizes[0] / FDIM;
    const int E = in_sizes[1] / 2;
    const int* src = ei;
    const int* dst = ei + E;

    float *dinv, *xws, *agg;
    int *cnt, *rowptr, *wptr, *eidx, *bsum;
    cudaGetSymbolAddress((void**)&dinv,   g_dinv);
    cudaGetSymbolAddress((void**)&xws,    g_xws);
    cudaGetSymbolAddress((void**)&agg,    g_agg);
    cudaGetSymbolAddress((void**)&cnt,    g_cnt);
    cudaGetSymbolAddress((void**)&rowptr, g_rowptr);
    cudaGetSymbolAddress((void**)&wptr,   g_wptr);
    cudaGetSymbolAddress((void**)&eidx,   g_eidx);
    cudaGetSymbolAddress((void**)&bsum,   g_bsum);

    const int TB = 256;
    const int nScanBlocks = (N + SCAN_B - 1) / SCAN_B;
    dim3 gblk(32, 8);
    const int rowBlocks = (N + RPB - 1) / RPB;
    const int gatherBlocks = (N * 32 + TB - 1) / TB;   // one warp per node

    // CSR build + degrees
    k_cnt_zero<<<(N + TB - 1) / TB, TB>>>(cnt, N);
    k_count   <<<(E + TB - 1) / TB, TB>>>(dst, cnt, E);
    k_dinv    <<<(N + TB - 1) / TB, TB>>>(cnt, dinv, N);
    k_scan1   <<<nScanBlocks, SCAN_B>>>(cnt, rowptr, bsum, N);
    k_scan2   <<<1, 128>>>(bsum, nScanBlocks);
    k_scan3   <<<(N + TB - 1) / TB, TB>>>(rowptr, wptr, bsum, N);
    k_fill    <<<(E + TB - 1) / TB, TB>>>(src, dst, wptr, eidx, E);

    // layer 1
    k_gemm64<false><<<rowBlocks, gblk>>>(x, W1, nullptr, dinv, xws, N);
    k_gather<<<gatherBlocks, TB>>>(rowptr, cnt, eidx, dinv,
                                   (const float2*)xws, (float2*)agg, N);
    // layer 2
    k_gemm64<true><<<rowBlocks, gblk>>>(agg, W2, b1, dinv, xws, N);
    k_gather<<<gatherBlocks, TB>>>(rowptr, cnt, eidx, dinv,
                                   (const float2*)xws, (float2*)agg, N);

    // head MLP
    k_head<<<rowBlocks, gblk>>>(agg, b2, dW1, db1, dW2, db2, out, N);
}

// round 6
// speedup vs baseline: 1.4865x; 1.0701x over previous
#include <cuda_runtime.h>
#include <cuda_fp16.h>
#include <cstdint>

#define NODES_MAX 100000
#define EDGES_MAX 1600000
#define FDIM 64
#define RPB 64             // rows per block
#define RPT 2              // rows per thread
#define CPG 8              // cols per thread
#define PITCH 66           // transposed smem pitch (floats)
#define SCAN_B 1024

// Scratch (allocation-free rule: __device__ globals)
__device__ float  g_dinv[NODES_MAX];
__device__ __half g_xws[NODES_MAX * FDIM];    // fp16 messages: (x @ W) * dinv[row]
__device__ float  g_agg[NODES_MAX * FDIM];    // gathered output (fp32)
__device__ int    g_cnt[NODES_MAX];
__device__ int    g_rowptr[NODES_MAX];
__device__ int    g_wptr[NODES_MAX];
__device__ int    g_eidx[EDGES_MAX];          // CSR: src ids grouped by dst
__device__ int    g_bsum[128];

// ---------------------------------------------------------------------------
// CSR build: count, dinv, warp-shuffle scan, fill
// ---------------------------------------------------------------------------
__global__ void k_cnt_zero(int* cnt, int n) {
    int i = blockIdx.x * blockDim.x + threadIdx.x;
    if (i < n) cnt[i] = 0;
}
__global__ void k_count(const int* __restrict__ dst, int* cnt, int E) {
    int e = blockIdx.x * blockDim.x + threadIdx.x;
    if (e < E) atomicAdd(&cnt[dst[e]], 1);
}
__global__ void k_dinv(const int* __restrict__ cnt, float* dinv, int n) {
    int i = blockIdx.x * blockDim.x + threadIdx.x;
    if (i < n) dinv[i] = rsqrtf((float)(cnt[i] + 1));
}
// block-level exclusive scan, warp-shuffle based
__global__ void k_scan1(const int* __restrict__ cnt, int* rowptr, int* bsum, int n) {
    __shared__ int wsum[32];
    int i = blockIdx.x * SCAN_B + threadIdx.x;
    int lane = threadIdx.x & 31;
    int wid  = threadIdx.x >> 5;
    int v = (i < n) ? cnt[i] : 0;
    int s = v;
    #pragma unroll
    for (int off = 1; off < 32; off <<= 1) {
        int t = __shfl_up_sync(0xffffffffu, s, off);
        if (lane >= off) s += t;
    }
    if (lane == 31) wsum[wid] = s;
    __syncthreads();
    if (wid == 0) {
        int w = wsum[lane];
        #pragma unroll
        for (int off = 1; off < 32; off <<= 1) {
            int t = __shfl_up_sync(0xffffffffu, w, off);
            if (lane >= off) w += t;
        }
        wsum[lane] = w;
    }
    __syncthreads();
    int blockoff = (wid > 0) ? wsum[wid - 1] : 0;
    if (i < n) rowptr[i] = blockoff + s - v;   // exclusive
    if (threadIdx.x == SCAN_B - 1) bsum[blockIdx.x] = blockoff + s;
}
__global__ void k_scan2(int* bsum, int nb) {
    int lane = threadIdx.x & 31;
    int wid  = threadIdx.x >> 5;     // 4 warps cover 128
    __shared__ int wsum[4];
    int v = (threadIdx.x < nb) ? bsum[threadIdx.x] : 0;
    int s = v;
    #pragma unroll
    for (int off = 1; off < 32; off <<= 1) {
        int t = __shfl_up_sync(0xffffffffu, s, off);
        if (lane >= off) s += t;
    }
    if (lane == 31) wsum[wid] = s;
    __syncthreads();
    int boff = 0;
    for (int w = 0; w < wid; w++) boff += wsum[w];
    if (threadIdx.x < nb) bsum[threadIdx.x] = boff + s - v;   // exclusive
}
__global__ void k_scan3(int* rowptr, int* wptr, const int* __restrict__ bsum, int n) {
    int i = blockIdx.x * blockDim.x + threadIdx.x;
    if (i < n) {
        int r = rowptr[i] + bsum[i >> 10];
        rowptr[i] = r;
        wptr[i] = r;
    }
}
__global__ void k_fill(const int* __restrict__ src, const int* __restrict__ dst,
                       int* wptr, int* eidx, int E) {
    int e = blockIdx.x * blockDim.x + threadIdx.x;
    if (e < E) {
        int d = dst[e];
        int p = atomicAdd(&wptr[d], 1);
        eidx[p] = src[e];
    }
}

// ---------------------------------------------------------------------------
// GEMM: xws[row] = half((f(in[row]) @ W) * dinv[row])   (PRE: f(v)=relu(v+bin))
// Block 64 rows x 64 cols, 256 threads, 2x8 register tile per thread.
// ---------------------------------------------------------------------------
template<bool PRE>
__global__ void __launch_bounds__(256, 6) k_gemm64(
        const float* __restrict__ in, const float* __restrict__ W,
        const float* __restrict__ bin, const float* __restrict__ dinv,
        __half* __restrict__ xws, int n) {
    __shared__ float Ws[FDIM * FDIM];
    __shared__ float rbT[FDIM * PITCH];
    const int lane = threadIdx.x;
    const int cg   = threadIdx.y;
    const int tid  = cg * 32 + lane;
    const int row0 = blockIdx.x * RPB;

    {
        const float4* W4 = (const float4*)W;
        float4* Ws4 = (float4*)Ws;
        #pragma unroll
        for (int i = tid; i < FDIM * FDIM / 4; i += 256) Ws4[i] = W4[i];
    }
    #pragma unroll
    for (int i = tid; i < RPB * FDIM; i += 256) {
        int r = i >> 6, c = i & 63;
        int row = row0 + r;
        float v = (row < n) ? in[row * FDIM + c] : 0.0f;
        if (PRE) v = fmaxf(v + bin[c], 0.0f);
        rbT[c * PITCH + r] = v;
    }
    __syncthreads();

    float acc[RPT][CPG];
    #pragma unroll
    for (int i = 0; i < RPT; i++)
        #pragma unroll
        for (int j = 0; j < CPG; j++) acc[i][j] = 0.0f;

    #pragma unroll
    for (int k = 0; k < FDIM; k++) {
        float2 a  = *(const float2*)&rbT[k * PITCH + lane * RPT];
        float4 w0 = *(const float4*)&Ws[k * FDIM + cg * CPG];
        float4 w1 = *(const float4*)&Ws[k * FDIM + cg * CPG + 4];
        const float ar[RPT] = {a.x, a.y};
        #pragma unroll
        for (int i = 0; i < RPT; i++) {
            acc[i][0] = fmaf(ar[i], w0.x, acc[i][0]);
            acc[i][1] = fmaf(ar[i], w0.y, acc[i][1]);
            acc[i][2] = fmaf(ar[i], w0.z, acc[i][2]);
            acc[i][3] = fmaf(ar[i], w0.w, acc[i][3]);
            acc[i][4] = fmaf(ar[i], w1.x, acc[i][4]);
            acc[i][5] = fmaf(ar[i], w1.y, acc[i][5]);
            acc[i][6] = fmaf(ar[i], w1.z, acc[i][6]);
            acc[i][7] = fmaf(ar[i], w1.w, acc[i][7]);
        }
    }

    #pragma unroll
    for (int i = 0; i < RPT; i++) {
        int row = row0 + lane * RPT + i;
        if (row >= n) break;
        float di = dinv[row];
        __half2 h[4];
        h[0] = __floats2half2_rn(acc[i][0] * di, acc[i][1] * di);
        h[1] = __floats2half2_rn(acc[i][2] * di, acc[i][3] * di);
        h[2] = __floats2half2_rn(acc[i][4] * di, acc[i][5] * di);
        h[3] = __floats2half2_rn(acc[i][6] * di, acc[i][7] * di);
        // 8 halfs = 16 bytes, one vector store
        *(uint4*)&xws[row * FDIM + cg * CPG] = *(uint4*)h;
    }
}

// ---------------------------------------------------------------------------
// CSR gather: agg[d] = dinv[d] * (xws[d] + Σ_{s in N(d)} xws[s])
// One warp per dst node; lane owns one half2 (2 of 64 cols) -> each gathered
// row is exactly one 128B L2 line. Accumulate fp32.
// ---------------------------------------------------------------------------
__global__ void k_gather(const int* __restrict__ rowptr, const int* __restrict__ cnt,
                         const int* __restrict__ eidx, const float* __restrict__ dinv,
                         const __half2* __restrict__ xws, float2* __restrict__ agg, int n) {
    int warp = (blockIdx.x * blockDim.x + threadIdx.x) >> 5;
    if (warp >= n) return;
    int lane = threadIdx.x & 31;
    int start = rowptr[warp];
    int deg   = cnt[warp];

    float2 acc = __half22float2(__ldg(&xws[warp * 32 + lane]));   // self loop
    for (int base = 0; base < deg; base += 32) {
        int m = min(32, deg - base);
        int e = 0;
        if (lane < m) e = eidx[start + base + lane];
        #pragma unroll 4
        for (int j = 0; j < m; j++) {
            int s = __shfl_sync(0xffffffffu, e, j);
            float2 v = __half22float2(__ldg(&xws[s * 32 + lane]));
            acc.x += v.x;
            acc.y += v.y;
        }
    }
    float nd = dinv[warp];
    acc.x *= nd; acc.y *= nd;
    agg[warp * 32 + lane] = acc;
}

// ---------------------------------------------------------------------------
// Head: v = relu(agg + b2); h = relu(v @ dW1 + db1); out = h @ dW2 + db2
// ---------------------------------------------------------------------------
__global__ void __launch_bounds__(256, 5) k_head(
        const float* __restrict__ agg, const float* __restrict__ b2,
        const float* __restrict__ dW1, const float* __restrict__ db1,
        const float* __restrict__ dW2, const float* __restrict__ db2,
        float* __restrict__ out, int n) {
    __shared__ float sW1[FDIM * FDIM];
    __shared__ float sW2[FDIM * 16];
    __shared__ float sb[2 * FDIM + 16];       // b2 | db1 | db2
    __shared__ float tT[FDIM * PITCH];        // transposed v, reused for h
    const int lane = threadIdx.x;
    const int cg   = threadIdx.y;
    const int tid  = cg * 32 + lane;
    const int row0 = blockIdx.x * RPB;

    {
        const float4* a4 = (const float4*)dW1;
        float4* s4 = (float4*)sW1;
        #pragma unroll
        for (int i = tid; i < FDIM * FDIM / 4; i += 256) s4[i] = a4[i];
        const float4* b4 = (const float4*)dW2;
        float4* t4 = (float4*)sW2;
        if (tid < FDIM * 16 / 4) t4[tid] = b4[tid];
        if (tid < 64)        sb[tid] = b2[tid];
        else if (tid < 128)  sb[tid] = db1[tid - 64];
        else if (tid < 144)  sb[tid] = db2[tid - 128];
    }

    #pragma unroll
    for (int i = tid; i < RPB * FDIM; i += 256) {
        int r = i >> 6, c = i & 63;
        int row = row0 + r;
        float x = (row < n) ? agg[row * FDIM + c] : 0.0f;
        tT[c * PITCH + r] = fmaxf(x + b2[c], 0.0f);
    }
    __syncthreads();

    float acc[RPT][CPG];
    #pragma unroll
    for (int i = 0; i < RPT; i++)
        #pragma unroll
        for (int j = 0; j < CPG; j++) acc[i][j] = 0.0f;

    #pragma unroll
    for (int k = 0; k < FDIM; k++) {
        float2 a  = *(const float2*)&tT[k * PITCH + lane * RPT];
        float4 w0 = *(const float4*)&sW1[k * FDIM + cg * CPG];
        float4 w1 = *(const float4*)&sW1[k * FDIM + cg * CPG + 4];
        const float ar[RPT] = {a.x, a.y};
        #pragma unroll
        for (int i = 0; i < RPT; i++) {
            acc[i][0] = fmaf(ar[i], w0.x, acc[i][0]);
            acc[i][1] = fmaf(ar[i], w0.y, acc[i][1]);
            acc[i][2] = fmaf(ar[i], w0.z, acc[i][2]);
            acc[i][3] = fmaf(ar[i], w0.w, acc[i][3]);
            acc[i][4] = fmaf(ar[i], w1.x, acc[i][4]);
            acc[i][5] = fmaf(ar[i], w1.y, acc[i][5]);
            acc[i][6] = fmaf(ar[i], w1.z, acc[i][6]);
            acc[i][7] = fmaf(ar[i], w1.w, acc[i][7]);
        }
    }
    __syncthreads();   // vT reads complete before overwrite with h

    #pragma unroll
    for (int i = 0; i < RPT; i++)
        #pragma unroll
        for (int j = 0; j < CPG; j++)
            tT[(cg * CPG + j) * PITCH + lane * RPT + i] =
                fmaxf(acc[i][j] + sb[64 + cg * CPG + j], 0.0f);
    __syncthreads();

    {
        float o[RPT][2];
        #pragma unroll
        for (int i = 0; i < RPT; i++) { o[i][0] = 0.0f; o[i][1] = 0.0f; }
        #pragma unroll
        for (int k = 0; k < FDIM; k++) {
            float2 a = *(const float2*)&tT[k * PITCH + lane * RPT];
            float2 w = *(const float2*)&sW2[k * 16 + cg * 2];
            const float ar[RPT] = {a.x, a.y};
            #pragma unroll
            for (int i = 0; i < RPT; i++) {
                o[i][0] = fmaf(ar[i], w.x, o[i][0]);
                o[i][1] = fmaf(ar[i], w.y, o[i][1]);
            }
        }
        #pragma unroll
        for (int i = 0; i < RPT; i++) {
            int row = row0 + lane * RPT + i;
            if (row >= n) break;
            float2 v;
            v.x = o[i][0] + sb[128 + cg * 2];
            v.y = o[i][1] + sb[128 + cg * 2 + 1];
            *(float2*)&out[row * 16 + cg * 2] = v;
        }
    }
}

// ---------------------------------------------------------------------------
extern "C" void kernel_launch(void* const* d_in, const int* in_sizes, int n_in,
                              void* d_out, int out_size) {
    const float* x   = (const float*)d_in[0];
    const int*   ei  = (const int*)  d_in[1];
    const float* W1  = (const float*)d_in[2];
    const float* b1  = (const float*)d_in[3];
    const float* W2  = (const float*)d_in[4];
    const float* b2  = (const float*)d_in[5];
    const float* dW1 = (const float*)d_in[6];
    const float* db1 = (const float*)d_in[7];
    const float* dW2 = (const float*)d_in[8];
    const float* db2 = (const float*)d_in[9];
    float* out = (float*)d_out;

    const int N = in_sizes[0] / FDIM;
    const int E = in_sizes[1] / 2;
    const int* src = ei;
    const int* dst = ei + E;

    float *dinv, *agg;
    __half* xws;
    int *cnt, *rowptr, *wptr, *eidx, *bsum;
    cudaGetSymbolAddress((void**)&dinv,   g_dinv);
    cudaGetSymbolAddress((void**)&xws,    g_xws);
    cudaGetSymbolAddress((void**)&agg,    g_agg);
    cudaGetSymbolAddress((void**)&cnt,    g_cnt);
    cudaGetSymbolAddress((void**)&rowptr, g_rowptr);
    cudaGetSymbolAddress((void**)&wptr,   g_wptr);
    cudaGetSymbolAddress((void**)&eidx,   g_eidx);
    cudaGetSymbolAddress((void**)&bsum,   g_bsum);

    const int TB = 256;
    const int nScanBlocks = (N + SCAN_B - 1) / SCAN_B;
    dim3 gblk(32, 8);
    const int rowBlocks = (N + RPB - 1) / RPB;
    const int gatherBlocks = (N * 32 + TB - 1) / TB;

    // CSR build + degrees
    k_cnt_zero<<<(N + TB - 1) / TB, TB>>>(cnt, N);
    k_count   <<<(E + TB - 1) / TB, TB>>>(dst, cnt, E);
    k_dinv    <<<(N + TB - 1) / TB, TB>>>(cnt, dinv, N);
    k_scan1   <<<nScanBlocks, SCAN_B>>>(cnt, rowptr, bsum, N);
    k_scan2   <<<1, 128>>>(bsum, nScanBlocks);
    k_scan3   <<<(N + TB - 1) / TB, TB>>>(rowptr, wptr, bsum, N);
    k_fill    <<<(E + TB - 1) / TB, TB>>>(src, dst, wptr, eidx, E);

    // layer 1
    k_gemm64<false><<<rowBlocks, gblk>>>(x, W1, nullptr, dinv, xws, N);
    k_gather<<<gatherBlocks, TB>>>(rowptr, cnt, eidx, dinv,
                                   (const __half2*)xws, (float2*)agg, N);
    // layer 2
    k_gemm64<true><<<rowBlocks, gblk>>>(agg, W2, b1, dinv, xws, N);
    k_gather<<<gatherBlocks, TB>>>(rowptr, cnt, eidx, dinv,
                                   (const __half2*)xws, (float2*)agg, N);

    // head MLP
    k_head<<<rowBlocks, gblk>>>(agg, b2, dW1, db1, dW2, db2, out, N);
}

// round 8
// speedup vs baseline: 1.4999x; 1.0090x over previous
#include <cuda_runtime.h>
#include <cuda_fp16.h>
#include <cstdint>

#define NODES_MAX 100000
#define EDGES_MAX 1600000
#define FDIM 64
#define RPB 64             // rows per block
#define RPT 2              // rows per thread
#define CPG 8              // cols per thread
#define PITCH 66           // transposed smem pitch (floats)
#define SCAN_B 1024

// Scratch (allocation-free rule: __device__ globals)
__device__ float  g_dinv[NODES_MAX];
__device__ __half g_xws[NODES_MAX * FDIM];    // fp16 messages: (x @ W) * dinv[row]
__device__ float  g_agg[NODES_MAX * FDIM];    // gathered output (fp32)
__device__ int    g_cnt[NODES_MAX];
__device__ int    g_rowptr[NODES_MAX];
__device__ int    g_wptr[NODES_MAX];
__device__ int    g_eidx[EDGES_MAX];          // CSR: src ids grouped by dst
__device__ int    g_bsum[128];

// ---------------------------------------------------------------------------
// CSR build: count, warp-shuffle scan (+dinv folded into scan3), fill
// ---------------------------------------------------------------------------
__global__ void k_cnt_zero(int* cnt, int n) {
    int i = blockIdx.x * blockDim.x + threadIdx.x;
    if (i < n) cnt[i] = 0;
}
__global__ void k_count(const int* __restrict__ dst, int* cnt, int E) {
    int e = blockIdx.x * blockDim.x + threadIdx.x;
    if (e < E) atomicAdd(&cnt[dst[e]], 1);
}
__global__ void k_scan1(const int* __restrict__ cnt, int* rowptr, int* bsum, int n) {
    __shared__ int wsum[32];
    int i = blockIdx.x * SCAN_B + threadIdx.x;
    int lane = threadIdx.x & 31;
    int wid  = threadIdx.x >> 5;
    int v = (i < n) ? cnt[i] : 0;
    int s = v;
    #pragma unroll
    for (int off = 1; off < 32; off <<= 1) {
        int t = __shfl_up_sync(0xffffffffu, s, off);
        if (lane >= off) s += t;
    }
    if (lane == 31) wsum[wid] = s;
    __syncthreads();
    if (wid == 0) {
        int w = wsum[lane];
        #pragma unroll
        for (int off = 1; off < 32; off <<= 1) {
            int t = __shfl_up_sync(0xffffffffu, w, off);
            if (lane >= off) w += t;
        }
        wsum[lane] = w;
    }
    __syncthreads();
    int blockoff = (wid > 0) ? wsum[wid - 1] : 0;
    if (i < n) rowptr[i] = blockoff + s - v;   // exclusive
    if (threadIdx.x == SCAN_B - 1) bsum[blockIdx.x] = blockoff + s;
}
__global__ void k_scan2(int* bsum, int nb) {
    int lane = threadIdx.x & 31;
    int wid  = threadIdx.x >> 5;
    __shared__ int wsum[4];
    int v = (threadIdx.x < nb) ? bsum[threadIdx.x] : 0;
    int s = v;
    #pragma unroll
    for (int off = 1; off < 32; off <<= 1) {
        int t = __shfl_up_sync(0xffffffffu, s, off);
        if (lane >= off) s += t;
    }
    if (lane == 31) wsum[wid] = s;
    __syncthreads();
    int boff = 0;
    for (int w = 0; w < wid; w++) boff += wsum[w];
    if (threadIdx.x < nb) bsum[threadIdx.x] = boff + s - v;   // exclusive
}
// scan finalize + wptr init + dinv (folded)
__global__ void k_scan3(int* rowptr, int* wptr, const int* __restrict__ bsum,
                        const int* __restrict__ cnt, float* dinv, int n) {
    int i = blockIdx.x * blockDim.x + threadIdx.x;
    if (i < n) {
        int r = rowptr[i] + bsum[i >> 10];
        rowptr[i] = r;
        wptr[i] = r;
        dinv[i] = rsqrtf((float)(cnt[i] + 1));
    }
}
__global__ void k_fill(const int* __restrict__ src, const int* __restrict__ dst,
                       int* wptr, int* eidx, int E) {
    int e = blockIdx.x * blockDim.x + threadIdx.x;
    if (e < E) {
        int d = dst[e];
        int p = atomicAdd(&wptr[d], 1);
        eidx[p] = src[e];
    }
}

// ---------------------------------------------------------------------------
// GEMM: xws[row] = half((f(in[row]) @ W) * dinv[row])   (PRE: f(v)=relu(v+bin))
// ---------------------------------------------------------------------------
template<bool PRE>
__global__ void __launch_bounds__(256, 6) k_gemm64(
        const float* __restrict__ in, const float* __restrict__ W,
        const float* __restrict__ bin, const float* __restrict__ dinv,
        __half* __restrict__ xws, int n) {
    __shared__ float Ws[FDIM * FDIM];
    __shared__ float rbT[FDIM * PITCH];
    const int lane = threadIdx.x;
    const int cg   = threadIdx.y;
    const int tid  = cg * 32 + lane;
    const int row0 = blockIdx.x * RPB;

    {
        const float4* W4 = (const float4*)W;
        float4* Ws4 = (float4*)Ws;
        #pragma unroll
        for (int i = tid; i < FDIM * FDIM / 4; i += 256) Ws4[i] = W4[i];
    }
    #pragma unroll
    for (int i = tid; i < RPB * FDIM; i += 256) {
        int r = i >> 6, c = i & 63;
        int row = row0 + r;
        float v = (row < n) ? in[row * FDIM + c] : 0.0f;
        if (PRE) v = fmaxf(v + bin[c], 0.0f);
        rbT[c * PITCH + r] = v;
    }
    __syncthreads();

    float acc[RPT][CPG];
    #pragma unroll
    for (int i = 0; i < RPT; i++)
        #pragma unroll
        for (int j = 0; j < CPG; j++) acc[i][j] = 0.0f;

    #pragma unroll
    for (int k = 0; k < FDIM; k++) {
        float2 a  = *(const float2*)&rbT[k * PITCH + lane * RPT];
        float4 w0 = *(const float4*)&Ws[k * FDIM + cg * CPG];
        float4 w1 = *(const float4*)&Ws[k * FDIM + cg * CPG + 4];
        const float ar[RPT] = {a.x, a.y};
        #pragma unroll
        for (int i = 0; i < RPT; i++) {
            acc[i][0] = fmaf(ar[i], w0.x, acc[i][0]);
            acc[i][1] = fmaf(ar[i], w0.y, acc[i][1]);
            acc[i][2] = fmaf(ar[i], w0.z, acc[i][2]);
            acc[i][3] = fmaf(ar[i], w0.w, acc[i][3]);
            acc[i][4] = fmaf(ar[i], w1.x, acc[i][4]);
            acc[i][5] = fmaf(ar[i], w1.y, acc[i][5]);
            acc[i][6] = fmaf(ar[i], w1.z, acc[i][6]);
            acc[i][7] = fmaf(ar[i], w1.w, acc[i][7]);
        }
    }

    #pragma unroll
    for (int i = 0; i < RPT; i++) {
        int row = row0 + lane * RPT + i;
        if (row >= n) break;
        float di = dinv[row];
        __half2 h[4];
        h[0] = __floats2half2_rn(acc[i][0] * di, acc[i][1] * di);
        h[1] = __floats2half2_rn(acc[i][2] * di, acc[i][3] * di);
        h[2] = __floats2half2_rn(acc[i][4] * di, acc[i][5] * di);
        h[3] = __floats2half2_rn(acc[i][6] * di, acc[i][7] * di);
        *(uint4*)&xws[row * FDIM + cg * CPG] = *(uint4*)h;
    }
}

// ---------------------------------------------------------------------------
// CSR gather: agg[d] = dinv[d] * (xws[d] + Σ_{s in N(d)} xws[s])
// One warp per dst node; lane owns one half2 -> each gathered row = one 128B
// L2 line. Unroll-8 bursts (8 independent LDG.32 in flight) + cross-batch
// eidx prefetch; fp32 accumulation.
// ---------------------------------------------------------------------------
__global__ void k_gather(const int* __restrict__ rowptr, const int* __restrict__ cnt,
                         const int* __restrict__ eidx, const float* __restrict__ dinv,
                         const __half2* __restrict__ xws, float2* __restrict__ agg, int n) {
    int warp = (blockIdx.x * blockDim.x + threadIdx.x) >> 5;
    if (warp >= n) return;
    int lane = threadIdx.x & 31;
    int start = rowptr[warp];
    int deg   = cnt[warp];

    float2 acc = __half22float2(__ldg(&xws[warp * 32 + lane]));   // self loop

    // first batch of edge ids
    int m = min(32, deg);
    int e = (lane < m) ? __ldg(&eidx[start + lane]) : 0;

    for (int base = 0; base < deg; base += 32) {
        int mcur = m;
        int ecur = e;
        // prefetch next batch before consuming this one
        int nbase = base + 32;
        if (nbase < deg) {
            m = min(32, deg - nbase);
            e = (lane < m) ? __ldg(&eidx[start + nbase + lane]) : 0;
        }

        int full = mcur & ~7;
        int j = 0;
        for (; j < full; j += 8) {
            float2 v[8];
            #pragma unroll
            for (int u = 0; u < 8; u++) {
                int s = __shfl_sync(0xffffffffu, ecur, j + u);
                v[u] = __half22float2(__ldg(&xws[s * 32 + lane]));
            }
            #pragma unroll
            for (int u = 0; u < 8; u++) {
                acc.x += v[u].x;
                acc.y += v[u].y;
            }
        }
        for (; j < mcur; j++) {
            int s = __shfl_sync(0xffffffffu, ecur, j);
            float2 v = __half22float2(__ldg(&xws[s * 32 + lane]));
            acc.x += v.x;
            acc.y += v.y;
        }
    }
    float nd = dinv[warp];
    acc.x *= nd; acc.y *= nd;
    agg[warp * 32 + lane] = acc;
}

// ---------------------------------------------------------------------------
// Head: v = relu(agg + b2); h = relu(v @ dW1 + db1); out = h @ dW2 + db2
// ---------------------------------------------------------------------------
__global__ void __launch_bounds__(256, 5) k_head(
        const float* __restrict__ agg, const float* __restrict__ b2,
        const float* __restrict__ dW1, const float* __restrict__ db1,
        const float* __restrict__ dW2, const float* __restrict__ db2,
        float* __restrict__ out, int n) {
    __shared__ float sW1[FDIM * FDIM];
    __shared__ float sW2[FDIM * 16];
    __shared__ float sb[2 * FDIM + 16];       // b2 | db1 | db2
    __shared__ float tT[FDIM * PITCH];        // transposed v, reused for h
    const int lane = threadIdx.x;
    const int cg   = threadIdx.y;
    const int tid  = cg * 32 + lane;
    const int row0 = blockIdx.x * RPB;

    {
        const float4* a4 = (const float4*)dW1;
        float4* s4 = (float4*)sW1;
        #pragma unroll
        for (int i = tid; i < FDIM * FDIM / 4; i += 256) s4[i] = a4[i];
        const float4* b4 = (const float4*)dW2;
        float4* t4 = (float4*)sW2;
        if (tid < FDIM * 16 / 4) t4[tid] = b4[tid];
        if (tid < 64)        sb[tid] = b2[tid];
        else if (tid < 128)  sb[tid] = db1[tid - 64];
        else if (tid < 144)  sb[tid] = db2[tid - 128];
    }

    #pragma unroll
    for (int i = tid; i < RPB * FDIM; i += 256) {
        int r = i >> 6, c = i & 63;
        int row = row0 + r;
        float x = (row < n) ? agg[row * FDIM + c] : 0.0f;
        tT[c * PITCH + r] = fmaxf(x + b2[c], 0.0f);
    }
    __syncthreads();

    float acc[RPT][CPG];
    #pragma unroll
    for (int i = 0; i < RPT; i++)
        #pragma unroll
        for (int j = 0; j < CPG; j++) acc[i][j] = 0.0f;

    #pragma unroll
    for (int k = 0; k < FDIM; k++) {
        float2 a  = *(const float2*)&tT[k * PITCH + lane * RPT];
        float4 w0 = *(const float4*)&sW1[k * FDIM + cg * CPG];
        float4 w1 = *(const float4*)&sW1[k * FDIM + cg * CPG + 4];
        const float ar[RPT] = {a.x, a.y};
        #pragma unroll
        for (int i = 0; i < RPT; i++) {
            acc[i][0] = fmaf(ar[i], w0.x, acc[i][0]);
            acc[i][1] = fmaf(ar[i], w0.y, acc[i][1]);
            acc[i][2] = fmaf(ar[i], w0.z, acc[i][2]);
            acc[i][3] = fmaf(ar[i], w0.w, acc[i][3]);
            acc[i][4] = fmaf(ar[i], w1.x, acc[i][4]);
            acc[i][5] = fmaf(ar[i], w1.y, acc[i][5]);
            acc[i][6] = fmaf(ar[i], w1.z, acc[i][6]);
            acc[i][7] = fmaf(ar[i], w1.w, acc[i][7]);
        }
    }
    __syncthreads();   // vT reads complete before overwrite with h

    #pragma unroll
    for (int i = 0; i < RPT; i++)
        #pragma unroll
        for (int j = 0; j < CPG; j++)
            tT[(cg * CPG + j) * PITCH + lane * RPT + i] =
                fmaxf(acc[i][j] + sb[64 + cg * CPG + j], 0.0f);
    __syncthreads();

    {
        float o[RPT][2];
        #pragma unroll
        for (int i = 0; i < RPT; i++) { o[i][0] = 0.0f; o[i][1] = 0.0f; }
        #pragma unroll
        for (int k = 0; k < FDIM; k++) {
            float2 a = *(const float2*)&tT[k * PITCH + lane * RPT];
            float2 w = *(const float2*)&sW2[k * 16 + cg * 2];
            const float ar[RPT] = {a.x, a.y};
            #pragma unroll
            for (int i = 0; i < RPT; i++) {
                o[i][0] = fmaf(ar[i], w.x, o[i][0]);
                o[i][1] = fmaf(ar[i], w.y, o[i][1]);
            }
        }
        #pragma unroll
        for (int i = 0; i < RPT; i++) {
            int row = row0 + lane * RPT + i;
            if (row >= n) break;
            float2 v;
            v.x = o[i][0] + sb[128 + cg * 2];
            v.y = o[i][1] + sb[128 + cg * 2 + 1];
            *(float2*)&out[row * 16 + cg * 2] = v;
        }
    }
}

// ---------------------------------------------------------------------------
extern "C" void kernel_launch(void* const* d_in, const int* in_sizes, int n_in,
                              void* d_out, int out_size) {
    const float* x   = (const float*)d_in[0];
    const int*   ei  = (const int*)  d_in[1];
    const float* W1  = (const float*)d_in[2];
    const float* b1  = (const float*)d_in[3];
    const float* W2  = (const float*)d_in[4];
    const float* b2  = (const float*)d_in[5];
    const float* dW1 = (const float*)d_in[6];
    const float* db1 = (const float*)d_in[7];
    const float* dW2 = (const float*)d_in[8];
    const float* db2 = (const float*)d_in[9];
    float* out = (float*)d_out;

    const int N = in_sizes[0] / FDIM;
    const int E = in_sizes[1] / 2;
    const int* src = ei;
    const int* dst = ei + E;

    float *dinv, *agg;
    __half* xws;
    int *cnt, *rowptr, *wptr, *eidx, *bsum;
    cudaGetSymbolAddress((void**)&dinv,   g_dinv);
    cudaGetSymbolAddress((void**)&xws,    g_xws);
    cudaGetSymbolAddress((void**)&agg,    g_agg);
    cudaGetSymbolAddress((void**)&cnt,    g_cnt);
    cudaGetSymbolAddress((void**)&rowptr, g_rowptr);
    cudaGetSymbolAddress((void**)&wptr,   g_wptr);
    cudaGetSymbolAddress((void**)&eidx,   g_eidx);
    cudaGetSymbolAddress((void**)&bsum,   g_bsum);

    const int TB = 256;
    const int nScanBlocks = (N + SCAN_B - 1) / SCAN_B;
    dim3 gblk(32, 8);
    const int rowBlocks = (N + RPB - 1) / RPB;
    const int gatherBlocks = (N * 32 + TB - 1) / TB;

    // CSR build (+dinv folded into scan3)
    k_cnt_zero<<<(N + TB - 1) / TB, TB>>>(cnt, N);
    k_count   <<<(E + TB - 1) / TB, TB>>>(dst, cnt, E);
    k_scan1   <<<nScanBlocks, SCAN_B>>>(cnt, rowptr, bsum, N);
    k_scan2   <<<1, 128>>>(bsum, nScanBlocks);
    k_scan3   <<<(N + TB - 1) / TB, TB>>>(rowptr, wptr, bsum, cnt, dinv, N);
    k_fill    <<<(E + TB - 1) / TB, TB>>>(src, dst, wptr, eidx, E);

    // layer 1
    k_gemm64<false><<<rowBlocks, gblk>>>(x, W1, nullptr, dinv, xws, N);
    k_gather<<<gatherBlocks, TB>>>(rowptr, cnt, eidx, dinv,
                                   (const __half2*)xws, (float2*)agg, N);
    // layer 2
    k_gemm64<true><<<rowBlocks, gblk>>>(agg, W2, b1, dinv, xws, N);
    k_gather<<<gatherBlocks, TB>>>(rowptr, cnt, eidx, dinv,
                                   (const __half2*)xws, (float2*)agg, N);

    // head MLP
    k_head<<<rowBlocks, gblk>>>(agg, b2, dW1, db1, dW2, db2, out, N);
}

// round 9
// speedup vs baseline: 1.5874x; 1.0584x over previous
#include <cuda_runtime.h>
#include <cuda_fp16.h>
#include <cstdint>

#define NODES_MAX 100000
#define EDGES_MAX 1600000
#define FDIM 64
#define RPB 64             // rows per block
#define RPT 2              // rows per thread
#define CPG 8              // cols per thread
#define PITCH 66           // transposed smem pitch (floats)
#define SCAN_B 1024

// Scratch (allocation-free rule: __device__ globals)
__device__ float  g_dinv[NODES_MAX];
__device__ __half g_xws1[NODES_MAX * FDIM];   // fp16 messages layer 1
__device__ __half g_xws2[NODES_MAX * FDIM];   // fp16 messages layer 2
__device__ int    g_cnt[NODES_MAX];
__device__ int    g_rowptr[NODES_MAX];
__device__ int    g_wptr[NODES_MAX];
__device__ int    g_eidx[EDGES_MAX];          // CSR: src ids grouped by dst
__device__ int    g_bsum[128];

// ---------------------------------------------------------------------------
// CSR build: count (cnt zeroed by memset), warp-shuffle scan (+dinv), fill
// ---------------------------------------------------------------------------
__global__ void k_count(const int* __restrict__ dst, int* cnt, int E) {
    int e = blockIdx.x * blockDim.x + threadIdx.x;
    if (e < E) atomicAdd(&cnt[dst[e]], 1);
}
__global__ void k_scan1(const int* __restrict__ cnt, int* rowptr, int* bsum, int n) {
    __shared__ int wsum[32];
    int i = blockIdx.x * SCAN_B + threadIdx.x;
    int lane = threadIdx.x & 31;
    int wid  = threadIdx.x >> 5;
    int v = (i < n) ? cnt[i] : 0;
    int s = v;
    #pragma unroll
    for (int off = 1; off < 32; off <<= 1) {
        int t = __shfl_up_sync(0xffffffffu, s, off);
        if (lane >= off) s += t;
    }
    if (lane == 31) wsum[wid] = s;
    __syncthreads();
    if (wid == 0) {
        int w = wsum[lane];
        #pragma unroll
        for (int off = 1; off < 32; off <<= 1) {
            int t = __shfl_up_sync(0xffffffffu, w, off);
            if (lane >= off) w += t;
        }
        wsum[lane] = w;
    }
    __syncthreads();
    int blockoff = (wid > 0) ? wsum[wid - 1] : 0;
    if (i < n) rowptr[i] = blockoff + s - v;   // exclusive
    if (threadIdx.x == SCAN_B - 1) bsum[blockIdx.x] = blockoff + s;
}
__global__ void k_scan2(int* bsum, int nb) {
    int lane = threadIdx.x & 31;
    int wid  = threadIdx.x >> 5;
    __shared__ int wsum[4];
    int v = (threadIdx.x < nb) ? bsum[threadIdx.x] : 0;
    int s = v;
    #pragma unroll
    for (int off = 1; off < 32; off <<= 1) {
        int t = __shfl_up_sync(0xffffffffu, s, off);
        if (lane >= off) s += t;
    }
    if (lane == 31) wsum[wid] = s;
    __syncthreads();
    int boff = 0;
    for (int w = 0; w < wid; w++) boff += wsum[w];
    if (threadIdx.x < nb) bsum[threadIdx.x] = boff + s - v;   // exclusive
}
__global__ void k_scan3(int* rowptr, int* wptr, const int* __restrict__ bsum,
                        const int* __restrict__ cnt, float* dinv, int n) {
    int i = blockIdx.x * blockDim.x + threadIdx.x;
    if (i < n) {
        int r = rowptr[i] + bsum[i >> 10];
        rowptr[i] = r;
        wptr[i] = r;
        dinv[i] = rsqrtf((float)(cnt[i] + 1));
    }
}
__global__ void k_fill(const int* __restrict__ src, const int* __restrict__ dst,
                       int* wptr, int* eidx, int E) {
    int e = blockIdx.x * blockDim.x + threadIdx.x;
    if (e < E) {
        int d = dst[e];
        int p = atomicAdd(&wptr[d], 1);
        eidx[p] = src[e];
    }
}

// ---------------------------------------------------------------------------
// Warp-level gather of one node row into a float2 (lane owns cols 2l, 2l+1).
// acc = xws[node] (self) + sum over CSR neighbors. fp32 accumulate.
// ---------------------------------------------------------------------------
__device__ __forceinline__ float2 gather_row(
        int node, int lane,
        const int* __restrict__ rowptr, const int* __restrict__ cnt,
        const int* __restrict__ eidx, const __half2* __restrict__ xws) {
    int start = rowptr[node];
    int deg   = cnt[node];
    float2 acc = __half22float2(__ldg(&xws[node * 32 + lane]));   // self loop

    int m = min(32, deg);
    int e = (lane < m) ? __ldg(&eidx[start + lane]) : 0;

    for (int base = 0; base < deg; base += 32) {
        int mcur = m;
        int ecur = e;
        int nbase = base + 32;
        if (nbase < deg) {
            m = min(32, deg - nbase);
            e = (lane < m) ? __ldg(&eidx[start + nbase + lane]) : 0;
        }
        int full = mcur & ~7;
        int j = 0;
        for (; j < full; j += 8) {
            float2 v[8];
            #pragma unroll
            for (int u = 0; u < 8; u++) {
                int s = __shfl_sync(0xffffffffu, ecur, j + u);
                v[u] = __half22float2(__ldg(&xws[s * 32 + lane]));
            }
            #pragma unroll
            for (int u = 0; u < 8; u++) {
                acc.x += v[u].x;
                acc.y += v[u].y;
            }
        }
        for (; j < mcur; j++) {
            int s = __shfl_sync(0xffffffffu, ecur, j);
            float2 v = __half22float2(__ldg(&xws[s * 32 + lane]));
            acc.x += v.x;
            acc.y += v.y;
        }
    }
    return acc;
}

// ---------------------------------------------------------------------------
// Layer-1 GEMM: xws1[row] = half((x[row] @ W1) * dinv[row])
// ---------------------------------------------------------------------------
__global__ void __launch_bounds__(256, 6) k_gemm1(
        const float* __restrict__ in, const float* __restrict__ W,
        const float* __restrict__ dinv, __half* __restrict__ xws, int n) {
    __shared__ float Ws[FDIM * FDIM];
    __shared__ float rbT[FDIM * PITCH];
    const int lane = threadIdx.x;
    const int cg   = threadIdx.y;
    const int tid  = cg * 32 + lane;
    const int row0 = blockIdx.x * RPB;

    {
        const float4* W4 = (const float4*)W;
        float4* Ws4 = (float4*)Ws;
        #pragma unroll
        for (int i = tid; i < FDIM * FDIM / 4; i += 256) Ws4[i] = W4[i];
    }
    #pragma unroll
    for (int i = tid; i < RPB * FDIM; i += 256) {
        int r = i >> 6, c = i & 63;
        int row = row0 + r;
        rbT[c * PITCH + r] = (row < n) ? in[row * FDIM + c] : 0.0f;
    }
    __syncthreads();

    float acc[RPT][CPG];
    #pragma unroll
    for (int i = 0; i < RPT; i++)
        #pragma unroll
        for (int j = 0; j < CPG; j++) acc[i][j] = 0.0f;

    #pragma unroll
    for (int k = 0; k < FDIM; k++) {
        float2 a  = *(const float2*)&rbT[k * PITCH + lane * RPT];
        float4 w0 = *(const float4*)&Ws[k * FDIM + cg * CPG];
        float4 w1 = *(const float4*)&Ws[k * FDIM + cg * CPG + 4];
        const float ar[RPT] = {a.x, a.y};
        #pragma unroll
        for (int i = 0; i < RPT; i++) {
            acc[i][0] = fmaf(ar[i], w0.x, acc[i][0]);
            acc[i][1] = fmaf(ar[i], w0.y, acc[i][1]);
            acc[i][2] = fmaf(ar[i], w0.z, acc[i][2]);
            acc[i][3] = fmaf(ar[i], w0.w, acc[i][3]);
            acc[i][4] = fmaf(ar[i], w1.x, acc[i][4]);
            acc[i][5] = fmaf(ar[i], w1.y, acc[i][5]);
            acc[i][6] = fmaf(ar[i], w1.z, acc[i][6]);
            acc[i][7] = fmaf(ar[i], w1.w, acc[i][7]);
        }
    }

    #pragma unroll
    for (int i = 0; i < RPT; i++) {
        int row = row0 + lane * RPT + i;
        if (row >= n) break;
        float di = dinv[row];
        __half2 h[4];
        h[0] = __floats2half2_rn(acc[i][0] * di, acc[i][1] * di);
        h[1] = __floats2half2_rn(acc[i][2] * di, acc[i][3] * di);
        h[2] = __floats2half2_rn(acc[i][4] * di, acc[i][5] * di);
        h[3] = __floats2half2_rn(acc[i][6] * di, acc[i][7] * di);
        *(uint4*)&xws[row * FDIM + cg * CPG] = *(uint4*)h;
    }
}

// ---------------------------------------------------------------------------
// Fused gather + layer-2 GEMM:
//   v[r] = relu(dinv[r] * gather(xws1, r) + b1)         (layer-1 activation)
//   xws2[r] = half((v @ W2) * dinv[r])
// Warp cg gathers nodes row0+cg*8 .. +8 into transposed smem, then all warps
// run the register-tiled GEMM. Gather LDG latency overlaps other warps' FMA.
// ---------------------------------------------------------------------------
__global__ void __launch_bounds__(256, 4) k_ggemm(
        const int* __restrict__ rowptr, const int* __restrict__ cnt,
        const int* __restrict__ eidx, const float* __restrict__ dinv,
        const __half2* __restrict__ xin, const float* __restrict__ bias,
        const float* __restrict__ W, __half* __restrict__ xout, int n) {
    __shared__ float Ws[FDIM * FDIM];
    __shared__ float tT[FDIM * PITCH];
    const int lane = threadIdx.x;
    const int cg   = threadIdx.y;
    const int tid  = cg * 32 + lane;
    const int row0 = blockIdx.x * RPB;

    {
        const float4* W4 = (const float4*)W;
        float4* Ws4 = (float4*)Ws;
        #pragma unroll
        for (int i = tid; i < FDIM * FDIM / 4; i += 256) Ws4[i] = W4[i];
    }

    // gather phase: warp cg owns 8 nodes
    const float b0 = __ldg(&bias[lane * 2]);
    const float b1 = __ldg(&bias[lane * 2 + 1]);
    #pragma unroll 1
    for (int nd = 0; nd < 8; nd++) {
        int r = cg * 8 + nd;
        int node = row0 + r;
        float2 v = make_float2(0.0f, 0.0f);
        if (node < n) {
            float2 acc = gather_row(node, lane, rowptr, cnt, eidx, xin);
            float ndv = __ldg(&dinv[node]);
            v.x = fmaxf(fmaf(acc.x, ndv, b0), 0.0f);
            v.y = fmaxf(fmaf(acc.y, ndv, b1), 0.0f);
        }
        tT[(lane * 2) * PITCH + r]     = v.x;
        tT[(lane * 2 + 1) * PITCH + r] = v.y;
    }
    __syncthreads();

    // gemm phase
    float acc[RPT][CPG];
    #pragma unroll
    for (int i = 0; i < RPT; i++)
        #pragma unroll
        for (int j = 0; j < CPG; j++) acc[i][j] = 0.0f;

    #pragma unroll
    for (int k = 0; k < FDIM; k++) {
        float2 a  = *(const float2*)&tT[k * PITCH + lane * RPT];
        float4 w0 = *(const float4*)&Ws[k * FDIM + cg * CPG];
        float4 w1 = *(const float4*)&Ws[k * FDIM + cg * CPG + 4];
        const float ar[RPT] = {a.x, a.y};
        #pragma unroll
        for (int i = 0; i < RPT; i++) {
            acc[i][0] = fmaf(ar[i], w0.x, acc[i][0]);
            acc[i][1] = fmaf(ar[i], w0.y, acc[i][1]);
            acc[i][2] = fmaf(ar[i], w0.z, acc[i][2]);
            acc[i][3] = fmaf(ar[i], w0.w, acc[i][3]);
            acc[i][4] = fmaf(ar[i], w1.x, acc[i][4]);
            acc[i][5] = fmaf(ar[i], w1.y, acc[i][5]);
            acc[i][6] = fmaf(ar[i], w1.z, acc[i][6]);
            acc[i][7] = fmaf(ar[i], w1.w, acc[i][7]);
        }
    }

    #pragma unroll
    for (int i = 0; i < RPT; i++) {
        int row = row0 + lane * RPT + i;
        if (row >= n) break;
        float di = dinv[row];
        __half2 h[4];
        h[0] = __floats2half2_rn(acc[i][0] * di, acc[i][1] * di);
        h[1] = __floats2half2_rn(acc[i][2] * di, acc[i][3] * di);
        h[2] = __floats2half2_rn(acc[i][4] * di, acc[i][5] * di);
        h[3] = __floats2half2_rn(acc[i][6] * di, acc[i][7] * di);
        *(uint4*)&xout[row * FDIM + cg * CPG] = *(uint4*)h;
    }
}

// ---------------------------------------------------------------------------
// Fused gather + head MLP:
//   v = relu(dinv * gather(xws2) + b2); h = relu(v @ dW1 + db1);
//   out = h @ dW2 + db2
// ---------------------------------------------------------------------------
__global__ void __launch_bounds__(256, 4) k_ghead(
        const int* __restrict__ rowptr, const int* __restrict__ cnt,
        const int* __restrict__ eidx, const float* __restrict__ dinv,
        const __half2* __restrict__ xin, const float* __restrict__ b2,
        const float* __restrict__ dW1, const float* __restrict__ db1,
        const float* __restrict__ dW2, const float* __restrict__ db2,
        float* __restrict__ out, int n) {
    __shared__ float sW1[FDIM * FDIM];
    __shared__ float sW2[FDIM * 16];
    __shared__ float sb[FDIM + 16];           // db1 | db2
    __shared__ float tT[FDIM * PITCH];
    const int lane = threadIdx.x;
    const int cg   = threadIdx.y;
    const int tid  = cg * 32 + lane;
    const int row0 = blockIdx.x * RPB;

    {
        const float4* a4 = (const float4*)dW1;
        float4* s4 = (float4*)sW1;
        #pragma unroll
        for (int i = tid; i < FDIM * FDIM / 4; i += 256) s4[i] = a4[i];
        const float4* b4 = (const float4*)dW2;
        float4* t4 = (float4*)sW2;
        if (tid < FDIM * 16 / 4) t4[tid] = b4[tid];
        if (tid < 64)       sb[tid] = db1[tid];
        else if (tid < 80)  sb[tid] = db2[tid - 64];
    }

    // gather phase: v = relu(dinv*gather + b2) -> transposed smem
    const float b0 = __ldg(&b2[lane * 2]);
    const float b1 = __ldg(&b2[lane * 2 + 1]);
    #pragma unroll 1
    for (int nd = 0; nd < 8; nd++) {
        int r = cg * 8 + nd;
        int node = row0 + r;
        float2 v = make_float2(0.0f, 0.0f);
        if (node < n) {
            float2 acc = gather_row(node, lane, rowptr, cnt, eidx, xin);
            float ndv = __ldg(&dinv[node]);
            v.x = fmaxf(fmaf(acc.x, ndv, b0), 0.0f);
            v.y = fmaxf(fmaf(acc.y, ndv, b1), 0.0f);
        }
        tT[(lane * 2) * PITCH + r]     = v.x;
        tT[(lane * 2 + 1) * PITCH + r] = v.y;
    }
    __syncthreads();

    // h = relu(v @ dW1 + db1)
    float acc[RPT][CPG];
    #pragma unroll
    for (int i = 0; i < RPT; i++)
        #pragma unroll
        for (int j = 0; j < CPG; j++) acc[i][j] = 0.0f;

    #pragma unroll
    for (int k = 0; k < FDIM; k++) {
        float2 a  = *(const float2*)&tT[k * PITCH + lane * RPT];
        float4 w0 = *(const float4*)&sW1[k * FDIM + cg * CPG];
        float4 w1 = *(const float4*)&sW1[k * FDIM + cg * CPG + 4];
        const float ar[RPT] = {a.x, a.y};
        #pragma unroll
        for (int i = 0; i < RPT; i++) {
            acc[i][0] = fmaf(ar[i], w0.x, acc[i][0]);
            acc[i][1] = fmaf(ar[i], w0.y, acc[i][1]);
            acc[i][2] = fmaf(ar[i], w0.z, acc[i][2]);
            acc[i][3] = fmaf(ar[i], w0.w, acc[i][3]);
            acc[i][4] = fmaf(ar[i], w1.x, acc[i][4]);
            acc[i][5] = fmaf(ar[i], w1.y, acc[i][5]);
            acc[i][6] = fmaf(ar[i], w1.z, acc[i][6]);
            acc[i][7] = fmaf(ar[i], w1.w, acc[i][7]);
        }
    }
    __syncthreads();   // vT reads complete before overwrite with h

    #pragma unroll
    for (int i = 0; i < RPT; i++)
        #pragma unroll
        for (int j = 0; j < CPG; j++)
            tT[(cg * CPG + j) * PITCH + lane * RPT + i] =
                fmaxf(acc[i][j] + sb[cg * CPG + j], 0.0f);
    __syncthreads();

    // out = h @ dW2 + db2
    {
        float o[RPT][2];
        #pragma unroll
        for (int i = 0; i < RPT; i++) { o[i][0] = 0.0f; o[i][1] = 0.0f; }
        #pragma unroll
        for (int k = 0; k < FDIM; k++) {
            float2 a = *(const float2*)&tT[k * PITCH + lane * RPT];
            float2 w = *(const float2*)&sW2[k * 16 + cg * 2];
            const float ar[RPT] = {a.x, a.y};
            #pragma unroll
            for (int i = 0; i < RPT; i++) {
                o[i][0] = fmaf(ar[i], w.x, o[i][0]);
                o[i][1] = fmaf(ar[i], w.y, o[i][1]);
            }
        }
        #pragma unroll
        for (int i = 0; i < RPT; i++) {
            int row = row0 + lane * RPT + i;
            if (row >= n) break;
            float2 v;
            v.x = o[i][0] + sb[64 + cg * 2];
            v.y = o[i][1] + sb[64 + cg * 2 + 1];
            *(float2*)&out[row * 16 + cg * 2] = v;
        }
    }
}

// ---------------------------------------------------------------------------
extern "C" void kernel_launch(void* const* d_in, const int* in_sizes, int n_in,
                              void* d_out, int out_size) {
    const float* x   = (const float*)d_in[0];
    const int*   ei  = (const int*)  d_in[1];
    const float* W1  = (const float*)d_in[2];
    const float* b1  = (const float*)d_in[3];
    const float* W2  = (const float*)d_in[4];
    const float* b2  = (const float*)d_in[5];
    const float* dW1 = (const float*)d_in[6];
    const float* db1 = (const float*)d_in[7];
    const float* dW2 = (const float*)d_in[8];
    const float* db2 = (const float*)d_in[9];
    float* out = (float*)d_out;

    const int N = in_sizes[0] / FDIM;
    const int E = in_sizes[1] / 2;
    const int* src = ei;
    const int* dst = ei + E;

    float* dinv;
    __half *xws1, *xws2;
    int *cnt, *rowptr, *wptr, *eidx, *bsum;
    cudaGetSymbolAddress((void**)&dinv,   g_dinv);
    cudaGetSymbolAddress((void**)&xws1,   g_xws1);
    cudaGetSymbolAddress((void**)&xws2,   g_xws2);
    cudaGetSymbolAddress((void**)&cnt,    g_cnt);
    cudaGetSymbolAddress((void**)&rowptr, g_rowptr);
    cudaGetSymbolAddress((void**)&wptr,   g_wptr);
    cudaGetSymbolAddress((void**)&eidx,   g_eidx);
    cudaGetSymbolAddress((void**)&bsum,   g_bsum);

    const int TB = 256;
    const int nScanBlocks = (N + SCAN_B - 1) / SCAN_B;
    dim3 gblk(32, 8);
    const int rowBlocks = (N + RPB - 1) / RPB;

    // CSR build
    cudaMemsetAsync(cnt, 0, N * sizeof(int));
    k_count<<<(E + TB - 1) / TB, TB>>>(dst, cnt, E);
    k_scan1<<<nScanBlocks, SCAN_B>>>(cnt, rowptr, bsum, N);
    k_scan2<<<1, 128>>>(bsum, nScanBlocks);
    k_scan3<<<(N + TB - 1) / TB, TB>>>(rowptr, wptr, bsum, cnt, dinv, N);
    k_fill <<<(E + TB - 1) / TB, TB>>>(src, dst, wptr, eidx, E);

    // layer 1 GEMM -> fused gather+layer2 GEMM -> fused gather+head
    k_gemm1<<<rowBlocks, gblk>>>(x, W1, dinv, xws1, N);
    k_ggemm<<<rowBlocks, gblk>>>(rowptr, cnt, eidx, dinv,
                                 (const __half2*)xws1, b1, W2, xws2, N);
    k_ghead<<<rowBlocks, gblk>>>(rowptr, cnt, eidx, dinv,
                                 (const __half2*)xws2, b2, dW1, db1, dW2, db2,
                                 out, N);
}